// round 2
// baseline (speedup 1.0000x reference)
#include <cuda_runtime.h>
#include <cstdint>
#include <math.h>

#define BB 4
#define TT 4096
#define CC 1024
#define EE 8
#define KKK 2
#define HH 4096
#define NN (BB*TT)          // 16384 tokens
#define CAP 8192            // per-expert row capacity (expected ~4096)

#define BM 128
#define BN 128
#define BK 16

// ---------------- device scratch (static: allocation-free rule) ----------------
__device__ int   g_cnt[EE];
__device__ float g_imp[EE];
__device__ int   g_rows[EE*CAP];        // expert bucket -> token id
__device__ int   g_tokrow[NN*KKK];      // (token,slot) -> global row (e*CAP+pos) or -1
__device__ float g_tv[NN*KKK];          // topk_vals flattened [t][s]
__device__ float g_h[(size_t)EE*CAP*HH];   // 1 GiB intermediate (relu(x@w1+b1))
__device__ float g_o[(size_t)EE*CAP*CC];   // 256 MB per-expert FFN outputs

// ---------------- init ----------------
__global__ void init_k() {
    int i = threadIdx.x;
    if (i < EE) { g_cnt[i] = 0; g_imp[i] = 0.f; }
}

// ---------------- router: logits, softmax, top-2, buckets ----------------
__global__ void router_k(const float* __restrict__ x,
                         const float* __restrict__ rw,
                         const float* __restrict__ rb) {
    int gw   = (int)((blockIdx.x * blockDim.x + threadIdx.x) >> 5);
    int lane = threadIdx.x & 31;
    if (gw >= NN) return;
    const float* xr = x + (size_t)gw * CC;

    float acc[EE];
#pragma unroll
    for (int e = 0; e < EE; e++) acc[e] = 0.f;
    for (int c = lane; c < CC; c += 32) {
        float xv = xr[c];
        const float* w = rw + c * EE;
#pragma unroll
        for (int e = 0; e < EE; e++) acc[e] = fmaf(xv, w[e], acc[e]);
    }
#pragma unroll
    for (int e = 0; e < EE; e++) {
#pragma unroll
        for (int off = 16; off; off >>= 1)
            acc[e] += __shfl_xor_sync(0xffffffffu, acc[e], off);
    }
    if (lane == 0) {
        float p[EE];
        float mx = -1e30f;
#pragma unroll
        for (int e = 0; e < EE; e++) { p[e] = acc[e] + rb[e]; mx = fmaxf(mx, p[e]); }
        float s = 0.f;
#pragma unroll
        for (int e = 0; e < EE; e++) { p[e] = expf(p[e] - mx); s += p[e]; }
        float inv = 1.f / s;
#pragma unroll
        for (int e = 0; e < EE; e++) p[e] *= inv;

        // stable top-2 (lowest index wins ties, matching jax.lax.top_k)
        int i0 = 0;
#pragma unroll
        for (int e = 1; e < EE; e++) if (p[e] > p[i0]) i0 = e;
        int i1 = (i0 == 0) ? 1 : 0;
#pragma unroll
        for (int e = 0; e < EE; e++) if (e != i0 && p[e] > p[i1]) i1 = e;

        g_tv[gw*2]   = p[i0];
        g_tv[gw*2+1] = p[i1];
        int es[2] = { i0, i1 };
#pragma unroll
        for (int s2 = 0; s2 < 2; s2++) {
            int e = es[s2];
            int pos = atomicAdd(&g_cnt[e], 1);
            if (pos < CAP) {
                g_rows[e*CAP + pos]  = gw;
                g_tokrow[gw*2 + s2]  = e*CAP + pos;
            } else {
                g_tokrow[gw*2 + s2]  = -1;
            }
        }
#pragma unroll
        for (int e = 0; e < EE; e++) atomicAdd(&g_imp[e], p[e]);
    }
}

// ---------------- grouped GEMM, tf32 mma.sync, 128x128x16 tiles ----------------
// MODE 1: h = relu(gather(x) @ w1[e] + b1[e])   (gather rows via g_rows)
// MODE 2: o = h @ w2[e] + b2[e]                  (dense rows of g_h)
template<int MODE>
__global__ __launch_bounds__(256)
void gemm_k(const float* __restrict__ Ax,
            const float* __restrict__ W,
            const float* __restrict__ bias) {
    constexpr int  Kdim  = (MODE == 1) ? CC : HH;
    constexpr int  outN  = (MODE == 1) ? HH : CC;
    constexpr bool RELU  = (MODE == 1);

    const float* A   = (MODE == 1) ? Ax : g_h;
    float*       Out = (MODE == 1) ? g_h : g_o;

    int e   = blockIdx.z;
    int cnt = min(g_cnt[e], CAP);
    int m0  = blockIdx.y * BM;
    if (m0 >= cnt) return;
    int n0  = blockIdx.x * BN;

    __shared__ uint32_t As[BM][BK];
    __shared__ uint32_t Bs[BK][BN];
    __shared__ int      arow[BM];

    int tid = threadIdx.x;
    for (int r = tid; r < BM; r += 256) {
        int idx = m0 + r;
        int g;
        if (MODE == 1) g = (idx < cnt) ? g_rows[e*CAP + idx] : 0;
        else           g = e*CAP + idx;
        arow[r] = g;
    }
    const float* Wb = W + (size_t)e * Kdim * outN;

    int lane = tid & 31, warp = tid >> 5;
    int wm = (warp & 3) * 32;      // 4 warps along M
    int wn = (warp >> 2) * 64;     // 2 warps along N

    float acc[2][8][4];
#pragma unroll
    for (int mt = 0; mt < 2; mt++)
#pragma unroll
        for (int nt = 0; nt < 8; nt++)
#pragma unroll
            for (int q = 0; q < 4; q++) acc[mt][nt][q] = 0.f;

    int a_r = tid >> 2;            // 0..63
    int a_c = (tid & 3) * 4;       // 0,4,8,12
    int b_k = tid >> 4;            // 0..15
    int b_n = (tid & 15) * 4;      // 0..60

    __syncthreads();

    for (int kt = 0; kt < Kdim; kt += BK) {
        // ---- load A tile (gathered rows), tf32-round, swizzled store ----
#pragma unroll
        for (int i = 0; i < 2; i++) {
            int r = a_r + i * 64;
            const float4 v = *(const float4*)(A + (size_t)arow[r] * Kdim + kt + a_c);
            uint32_t t0, t1, t2, t3;
            asm("cvt.rna.tf32.f32 %0, %1;" : "=r"(t0) : "f"(v.x));
            asm("cvt.rna.tf32.f32 %0, %1;" : "=r"(t1) : "f"(v.y));
            asm("cvt.rna.tf32.f32 %0, %1;" : "=r"(t2) : "f"(v.z));
            asm("cvt.rna.tf32.f32 %0, %1;" : "=r"(t3) : "f"(v.w));
            int kc = a_c ^ (4 * (r & 3));
            As[r][kc] = t0; As[r][kc+1] = t1; As[r][kc+2] = t2; As[r][kc+3] = t3;
        }
        // ---- load B tile (weights), tf32-round, swizzled store ----
#pragma unroll
        for (int i = 0; i < 2; i++) {
            int n = b_n + i * 64;
            const float4 v = *(const float4*)(Wb + (size_t)(kt + b_k) * outN + n0 + n);
            uint32_t t0, t1, t2, t3;
            asm("cvt.rna.tf32.f32 %0, %1;" : "=r"(t0) : "f"(v.x));
            asm("cvt.rna.tf32.f32 %0, %1;" : "=r"(t1) : "f"(v.y));
            asm("cvt.rna.tf32.f32 %0, %1;" : "=r"(t2) : "f"(v.z));
            asm("cvt.rna.tf32.f32 %0, %1;" : "=r"(t3) : "f"(v.w));
            int nc = n ^ (8 * (b_k & 3));
            Bs[b_k][nc] = t0; Bs[b_k][nc+1] = t1; Bs[b_k][nc+2] = t2; Bs[b_k][nc+3] = t3;
        }
        __syncthreads();

#pragma unroll
        for (int ks = 0; ks < BK; ks += 8) {
            uint32_t af[2][4], bf[8][2];
#pragma unroll
            for (int mt = 0; mt < 2; mt++) {
                int m  = wm + mt * 16 + (lane >> 2);
                int sw = 4 * (m & 3);
                int k  = ks + (lane & 3);
                af[mt][0] = As[m    ][ k      ^ sw];
                af[mt][1] = As[m + 8][ k      ^ sw];
                af[mt][2] = As[m    ][(k + 4) ^ sw];
                af[mt][3] = As[m + 8][(k + 4) ^ sw];
            }
            int kb  = ks + (lane & 3);
            int swb = 8 * (kb & 3);
#pragma unroll
            for (int nt = 0; nt < 8; nt++) {
                int n = wn + nt * 8 + (lane >> 2);
                bf[nt][0] = Bs[kb    ][n ^ swb];
                bf[nt][1] = Bs[kb + 4][n ^ swb];
            }
#pragma unroll
            for (int mt = 0; mt < 2; mt++)
#pragma unroll
                for (int nt = 0; nt < 8; nt++) {
                    asm volatile(
                        "mma.sync.aligned.m16n8k8.row.col.f32.tf32.tf32.f32 "
                        "{%0,%1,%2,%3}, {%4,%5,%6,%7}, {%8,%9}, {%0,%1,%2,%3};"
                        : "+f"(acc[mt][nt][0]), "+f"(acc[mt][nt][1]),
                          "+f"(acc[mt][nt][2]), "+f"(acc[mt][nt][3])
                        : "r"(af[mt][0]), "r"(af[mt][1]), "r"(af[mt][2]), "r"(af[mt][3]),
                          "r"(bf[nt][0]), "r"(bf[nt][1]));
                }
        }
        __syncthreads();
    }

    // ---- epilogue: bias (+relu), write per-expert scratch ----
#pragma unroll
    for (int mt = 0; mt < 2; mt++)
#pragma unroll
        for (int nt = 0; nt < 8; nt++) {
            int mrow = wm + mt * 16 + (lane >> 2);
            int col  = n0 + wn + nt * 8 + 2 * (lane & 3);
            float bc0 = bias[e * outN + col];
            float bc1 = bias[e * outN + col + 1];
            float v00 = acc[mt][nt][0] + bc0;
            float v01 = acc[mt][nt][1] + bc1;
            float v10 = acc[mt][nt][2] + bc0;
            float v11 = acc[mt][nt][3] + bc1;
            if (RELU) {
                v00 = fmaxf(v00, 0.f); v01 = fmaxf(v01, 0.f);
                v10 = fmaxf(v10, 0.f); v11 = fmaxf(v11, 0.f);
            }
            size_t o0 = ((size_t)(e * CAP + m0 + mrow)) * outN + col;
            Out[o0]     = v00; Out[o0 + 1] = v01;
            size_t o1 = o0 + (size_t)8 * outN;
            Out[o1]     = v10; Out[o1 + 1] = v11;
        }
}

// ---------------- combine: out[t] = w_tok[t] * (O[row0] + O[row1]) ----------------
__global__ void combine_k(float* __restrict__ out) {
    size_t i = (size_t)blockIdx.x * blockDim.x + threadIdx.x; // float4 index
    if (i >= (size_t)NN * CC / 4) return;
    int t  = (int)(i / (CC / 4));
    int c  = (int)(i % (CC / 4)) * 4;
    float w = g_tv[t];                 // faithful: w_tok[t] = topk_vals.flat[t]
    int r0 = g_tokrow[t * 2];
    int r1 = g_tokrow[t * 2 + 1];
    float4 a = make_float4(0.f, 0.f, 0.f, 0.f);
    float4 b = make_float4(0.f, 0.f, 0.f, 0.f);
    if (r0 >= 0) a = *(const float4*)(g_o + (size_t)r0 * CC + c);
    if (r1 >= 0) b = *(const float4*)(g_o + (size_t)r1 * CC + c);
    float4 o;
    o.x = w * (a.x + b.x); o.y = w * (a.y + b.y);
    o.z = w * (a.z + b.z); o.w = w * (a.w + b.w);
    *(float4*)(out + (size_t)t * CC + c) = o;
}

// ---------------- aux loss ----------------
__global__ void aux_k(float* __restrict__ out, int out_size) {
    int lane = threadIdx.x;
    float v = 0.f;
    if (lane < EE)
        v = (g_imp[lane] / (float)NN) * ((float)g_cnt[lane] / (float)(NN * KKK));
#pragma unroll
    for (int off = 16; off; off >>= 1) v += __shfl_xor_sync(0xffffffffu, v, off);
    if (lane == 0) {
        if (out_size > NN * CC)     out[(size_t)NN * CC] = v;
        if (out_size - 1 > NN * CC) out[(size_t)out_size - 1] = v;
    }
}

// ---------------- launch ----------------
extern "C" void kernel_launch(void* const* d_in, const int* in_sizes, int n_in,
                              void* d_out, int out_size) {
    const float* x  = (const float*)d_in[0];
    const float* rw = (const float*)d_in[1];
    const float* rb = (const float*)d_in[2];
    const float* w1 = (const float*)d_in[3];
    const float* b1 = (const float*)d_in[4];
    const float* w2 = (const float*)d_in[5];
    const float* b2 = (const float*)d_in[6];
    float* out = (float*)d_out;

    init_k<<<1, 32>>>();
    router_k<<<NN / 8, 256>>>(x, rw, rb);
    gemm_k<1><<<dim3(HH / BN, CAP / BM, EE), 256>>>(x, w1, b1);
    gemm_k<2><<<dim3(CC / BN, CAP / BM, EE), 256>>>(nullptr, w2, b2);
    combine_k<<<(int)(((size_t)NN * CC / 4 + 255) / 256), 256>>>(out);
    aux_k<<<1, 32>>>(out, out_size);
}

// round 3
// speedup vs baseline: 1.8586x; 1.8586x over previous
#include <cuda_runtime.h>
#include <cstdint>
#include <math.h>

#define BB 4
#define TT 4096
#define CC 1024
#define EE 8
#define KKK 2
#define HH 4096
#define NN (BB*TT)          // 16384 tokens
#define CAP 8192            // per-expert row capacity (expected ~4096)

#define BM 128
#define BN 128
#define BK 32
#define STAGES 3
#define STAGE_FLOATS (BM*BK + BK*BN)     // 8192 floats = 32KB
#define SMEM_BYTES (STAGES*STAGE_FLOATS*4)  // 98304

// ---------------- device scratch (static: allocation-free rule) ----------------
__device__ int   g_cnt[EE];
__device__ float g_imp[EE];
__device__ int   g_rows[EE*CAP];
__device__ int   g_tokrow[NN*KKK];
__device__ float g_tv[NN*KKK];
__device__ float g_h[(size_t)EE*CAP*HH];      // 1 GiB intermediate
__device__ float g_o[(size_t)EE*CAP*CC];      // 256 MB per-expert outputs
__device__ float g_xc[(size_t)NN*CC];         // tf32-rounded x
__device__ float g_w1c[(size_t)EE*CC*HH];     // tf32-rounded w1
__device__ float g_w2c[(size_t)EE*HH*CC];     // tf32-rounded w2

// ---------------- init ----------------
__global__ void init_k() {
    int i = threadIdx.x;
    if (i < EE) { g_cnt[i] = 0; g_imp[i] = 0.f; }
}

// ---------------- tf32 pre-convert (round-to-nearest, keeps fp32 bit layout) ----
__global__ void cvt_k(const float4* __restrict__ src, float4* __restrict__ dst, int n4) {
    int i = blockIdx.x * blockDim.x + threadIdx.x;
    if (i >= n4) return;
    float4 v = src[i];
    uint32_t t0, t1, t2, t3;
    asm("cvt.rna.tf32.f32 %0, %1;" : "=r"(t0) : "f"(v.x));
    asm("cvt.rna.tf32.f32 %0, %1;" : "=r"(t1) : "f"(v.y));
    asm("cvt.rna.tf32.f32 %0, %1;" : "=r"(t2) : "f"(v.z));
    asm("cvt.rna.tf32.f32 %0, %1;" : "=r"(t3) : "f"(v.w));
    float4 o;
    o.x = __uint_as_float(t0); o.y = __uint_as_float(t1);
    o.z = __uint_as_float(t2); o.w = __uint_as_float(t3);
    dst[i] = o;
}

// ---------------- router ----------------
__global__ void router_k(const float* __restrict__ x,
                         const float* __restrict__ rw,
                         const float* __restrict__ rb) {
    int gw   = (int)((blockIdx.x * blockDim.x + threadIdx.x) >> 5);
    int lane = threadIdx.x & 31;
    if (gw >= NN) return;
    const float* xr = x + (size_t)gw * CC;

    float acc[EE];
#pragma unroll
    for (int e = 0; e < EE; e++) acc[e] = 0.f;
    for (int c = lane; c < CC; c += 32) {
        float xv = xr[c];
        const float* w = rw + c * EE;
#pragma unroll
        for (int e = 0; e < EE; e++) acc[e] = fmaf(xv, w[e], acc[e]);
    }
#pragma unroll
    for (int e = 0; e < EE; e++) {
#pragma unroll
        for (int off = 16; off; off >>= 1)
            acc[e] += __shfl_xor_sync(0xffffffffu, acc[e], off);
    }
    if (lane == 0) {
        float p[EE];
        float mx = -1e30f;
#pragma unroll
        for (int e = 0; e < EE; e++) { p[e] = acc[e] + rb[e]; mx = fmaxf(mx, p[e]); }
        float s = 0.f;
#pragma unroll
        for (int e = 0; e < EE; e++) { p[e] = expf(p[e] - mx); s += p[e]; }
        float inv = 1.f / s;
#pragma unroll
        for (int e = 0; e < EE; e++) p[e] *= inv;

        int i0 = 0;
#pragma unroll
        for (int e = 1; e < EE; e++) if (p[e] > p[i0]) i0 = e;
        int i1 = (i0 == 0) ? 1 : 0;
#pragma unroll
        for (int e = 0; e < EE; e++) if (e != i0 && p[e] > p[i1]) i1 = e;

        g_tv[gw*2]   = p[i0];
        g_tv[gw*2+1] = p[i1];
        int es[2] = { i0, i1 };
#pragma unroll
        for (int s2 = 0; s2 < 2; s2++) {
            int e = es[s2];
            int pos = atomicAdd(&g_cnt[e], 1);
            if (pos < CAP) {
                g_rows[e*CAP + pos]  = gw;
                g_tokrow[gw*2 + s2]  = e*CAP + pos;
            } else {
                g_tokrow[gw*2 + s2]  = -1;
            }
        }
#pragma unroll
        for (int e = 0; e < EE; e++) atomicAdd(&g_imp[e], p[e]);
    }
}

// ---------------- cp.async helpers ----------------
__device__ __forceinline__ void cp16(uint32_t dst, const void* src) {
    asm volatile("cp.async.cg.shared.global [%0], [%1], 16;\n" :: "r"(dst), "l"(src));
}
__device__ __forceinline__ void cp_commit() {
    asm volatile("cp.async.commit_group;\n" ::: "memory");
}
template<int N> __device__ __forceinline__ void cp_wait() {
    asm volatile("cp.async.wait_group %0;\n" :: "n"(N) : "memory");
}

// ---------------- grouped GEMM, tf32 mma.sync, 128x128x32, 3-stage cp.async ----
// MODE 1: h = relu(gather(xc) @ w1c[e] + b1[e])
// MODE 2: o = h @ w2c[e] + b2[e]
template<int MODE>
__global__ __launch_bounds__(256, 2)
void gemm_k(const float* __restrict__ bias) {
    constexpr int  Kdim  = (MODE == 1) ? CC : HH;
    constexpr int  outN  = (MODE == 1) ? HH : CC;
    constexpr bool RELU  = (MODE == 1);
    constexpr int  ITERS = Kdim / BK;

    const float* A  = (MODE == 1) ? g_xc : g_h;
    const float* Wc = (MODE == 1) ? g_w1c : g_w2c;
    float*       Out = (MODE == 1) ? g_h : g_o;

    int e   = blockIdx.z;
    int cnt = min(g_cnt[e], CAP);
    int m0  = blockIdx.y * BM;
    if (m0 >= cnt) return;
    int n0  = blockIdx.x * BN;

    extern __shared__ float smem_buf[];
    __shared__ int arow[BM];

    int tid  = threadIdx.x;
    int lane = tid & 31, warp = tid >> 5;

    if (tid < BM) {
        int idx = m0 + tid;
        int g;
        if (MODE == 1) g = (idx < cnt) ? g_rows[e*CAP + idx] : 0;
        else           g = e*CAP + idx;
        arow[tid] = g;
    }
    __syncthreads();

    const float* Wb = Wc + (size_t)e * Kdim * outN + n0;

    // ---- per-thread cp.async descriptors ----
    // A: 128 rows x 8 chunks(16B). thread -> rows (tid>>3)+32i, chunk tid&7
    int jA = tid & 7;
    int rA = tid >> 3;
    const float* aptr[4];
    uint32_t     adst[4];
#pragma unroll
    for (int i = 0; i < 4; i++) {
        int r = rA + 32*i;
        aptr[i] = A + (size_t)arow[r] * Kdim + jA*4;
        adst[i] = (uint32_t)(r*BK + ((jA ^ (r & 7)) << 2)) * 4u;
    }
    // B: 32 rows x 32 chunks(16B). thread -> rows (tid>>5)+8i, chunk tid&31
    int jB = tid & 31;
    int kB = tid >> 5;
    const float* bptr[4];
    uint32_t     bdst[4];
#pragma unroll
    for (int i = 0; i < 4; i++) {
        int kb = kB + 8*i;
        bptr[i] = Wb + (size_t)kb * outN + jB*4;
        bdst[i] = (uint32_t)(BM*BK + kb*BN + ((jB ^ ((kb & 3) << 1)) << 2)) * 4u;
    }

    uint32_t smbase = (uint32_t)__cvta_generic_to_shared(smem_buf);

    auto issue = [&](int stage) {
        uint32_t s = smbase + (uint32_t)stage * (STAGE_FLOATS * 4);
#pragma unroll
        for (int i = 0; i < 4; i++) { cp16(s + adst[i], aptr[i]); aptr[i] += BK; }
#pragma unroll
        for (int i = 0; i < 4; i++) { cp16(s + bdst[i], bptr[i]); bptr[i] += (size_t)BK * outN; }
    };

    issue(0); cp_commit();
    issue(1); cp_commit();

    int wm = (warp & 3) * 32;
    int wn = (warp >> 2) * 64;
    int q  = lane & 3;
    int gg = lane >> 2;

    float acc[2][8][4];
#pragma unroll
    for (int mt = 0; mt < 2; mt++)
#pragma unroll
        for (int nt = 0; nt < 8; nt++)
#pragma unroll
            for (int p = 0; p < 4; p++) acc[mt][nt][p] = 0.f;

    for (int it = 0; it < ITERS; ++it) {
        cp_wait<1>();
        __syncthreads();
        if (it + 2 < ITERS) issue((it + 2) % STAGES);
        cp_commit();

        const uint32_t* As = (const uint32_t*)(smem_buf + (it % STAGES) * STAGE_FLOATS);
        const uint32_t* Bs = As + BM*BK;

#pragma unroll
        for (int ks = 0; ks < BK; ks += 8) {
            uint32_t af[2][4], bf[8][2];
            int c0 = ks >> 2;        // chunk for k=ks+q
#pragma unroll
            for (int mt = 0; mt < 2; mt++) {
                int m = wm + mt*16 + gg;
                int sw = m & 7;
                af[mt][0] = As[m*BK       + (( c0      ^ sw) << 2) + q];
                af[mt][1] = As[(m+8)*BK   + (( c0      ^ ((m+8)&7)) << 2) + q];
                af[mt][2] = As[m*BK       + (((c0 + 1) ^ sw) << 2) + q];
                af[mt][3] = As[(m+8)*BK   + (((c0 + 1) ^ ((m+8)&7)) << 2) + q];
            }
            int kb  = ks + q;
            int swb = (kb & 3) << 1;
#pragma unroll
            for (int nt = 0; nt < 8; nt++) {
                int n = wn + nt*8 + gg;
                uint32_t col = (((n >> 2) ^ swb) << 2) + (n & 3);
                bf[nt][0] = Bs[kb*BN       + col];
                bf[nt][1] = Bs[(kb+4)*BN   + col];
            }
#pragma unroll
            for (int mt = 0; mt < 2; mt++)
#pragma unroll
                for (int nt = 0; nt < 8; nt++) {
                    asm volatile(
                        "mma.sync.aligned.m16n8k8.row.col.f32.tf32.tf32.f32 "
                        "{%0,%1,%2,%3}, {%4,%5,%6,%7}, {%8,%9}, {%0,%1,%2,%3};"
                        : "+f"(acc[mt][nt][0]), "+f"(acc[mt][nt][1]),
                          "+f"(acc[mt][nt][2]), "+f"(acc[mt][nt][3])
                        : "r"(af[mt][0]), "r"(af[mt][1]), "r"(af[mt][2]), "r"(af[mt][3]),
                          "r"(bf[nt][0]), "r"(bf[nt][1]));
                }
        }
    }

    // ---- epilogue: bias (+relu, +tf32-round for h) ----
#pragma unroll
    for (int mt = 0; mt < 2; mt++)
#pragma unroll
        for (int nt = 0; nt < 8; nt++) {
            int mrow = wm + mt*16 + gg;
            int col  = n0 + wn + nt*8 + 2*q;
            float bc0 = bias[e * outN + col];
            float bc1 = bias[e * outN + col + 1];
            float v00 = acc[mt][nt][0] + bc0;
            float v01 = acc[mt][nt][1] + bc1;
            float v10 = acc[mt][nt][2] + bc0;
            float v11 = acc[mt][nt][3] + bc1;
            if (RELU) {
                v00 = fmaxf(v00, 0.f); v01 = fmaxf(v01, 0.f);
                v10 = fmaxf(v10, 0.f); v11 = fmaxf(v11, 0.f);
                uint32_t t;
                asm("cvt.rna.tf32.f32 %0, %1;" : "=r"(t) : "f"(v00)); v00 = __uint_as_float(t);
                asm("cvt.rna.tf32.f32 %0, %1;" : "=r"(t) : "f"(v01)); v01 = __uint_as_float(t);
                asm("cvt.rna.tf32.f32 %0, %1;" : "=r"(t) : "f"(v10)); v10 = __uint_as_float(t);
                asm("cvt.rna.tf32.f32 %0, %1;" : "=r"(t) : "f"(v11)); v11 = __uint_as_float(t);
            }
            size_t o0 = ((size_t)(e * CAP + m0 + mrow)) * outN + col;
            Out[o0]     = v00; Out[o0 + 1] = v01;
            size_t o1 = o0 + (size_t)8 * outN;
            Out[o1]     = v10; Out[o1 + 1] = v11;
        }
}

// ---------------- combine ----------------
__global__ void combine_k(float* __restrict__ out) {
    size_t i = (size_t)blockIdx.x * blockDim.x + threadIdx.x;
    if (i >= (size_t)NN * CC / 4) return;
    int t  = (int)(i / (CC / 4));
    int c  = (int)(i % (CC / 4)) * 4;
    float w = g_tv[t];
    int r0 = g_tokrow[t * 2];
    int r1 = g_tokrow[t * 2 + 1];
    float4 a = make_float4(0.f, 0.f, 0.f, 0.f);
    float4 b = make_float4(0.f, 0.f, 0.f, 0.f);
    if (r0 >= 0) a = *(const float4*)(g_o + (size_t)r0 * CC + c);
    if (r1 >= 0) b = *(const float4*)(g_o + (size_t)r1 * CC + c);
    float4 o;
    o.x = w * (a.x + b.x); o.y = w * (a.y + b.y);
    o.z = w * (a.z + b.z); o.w = w * (a.w + b.w);
    *(float4*)(out + (size_t)t * CC + c) = o;
}

// ---------------- aux loss ----------------
__global__ void aux_k(float* __restrict__ out, int out_size) {
    int lane = threadIdx.x;
    float v = 0.f;
    if (lane < EE)
        v = (g_imp[lane] / (float)NN) * ((float)g_cnt[lane] / (float)(NN * KKK));
#pragma unroll
    for (int off = 16; off; off >>= 1) v += __shfl_xor_sync(0xffffffffu, v, off);
    if (lane == 0) {
        if (out_size > NN * CC)     out[(size_t)NN * CC] = v;
        if (out_size - 1 > NN * CC) out[(size_t)out_size - 1] = v;
    }
}

// ---------------- launch ----------------
extern "C" void kernel_launch(void* const* d_in, const int* in_sizes, int n_in,
                              void* d_out, int out_size) {
    const float* x  = (const float*)d_in[0];
    const float* rw = (const float*)d_in[1];
    const float* rb = (const float*)d_in[2];
    const float* w1 = (const float*)d_in[3];
    const float* b1 = (const float*)d_in[4];
    const float* w2 = (const float*)d_in[5];
    const float* b2 = (const float*)d_in[6];
    float* out = (float*)d_out;

    cudaFuncSetAttribute(gemm_k<1>, cudaFuncAttributeMaxDynamicSharedMemorySize, SMEM_BYTES);
    cudaFuncSetAttribute(gemm_k<2>, cudaFuncAttributeMaxDynamicSharedMemorySize, SMEM_BYTES);

    float* w1c; cudaGetSymbolAddress((void**)&w1c, g_w1c);
    float* w2c; cudaGetSymbolAddress((void**)&w2c, g_w2c);
    float* xc;  cudaGetSymbolAddress((void**)&xc,  g_xc);

    init_k<<<1, 32>>>();
    router_k<<<NN / 8, 256>>>(x, rw, rb);

    {
        int n4 = (int)((size_t)NN * CC / 4);
        cvt_k<<<(n4 + 255) / 256, 256>>>((const float4*)x, (float4*)xc, n4);
    }
    {
        int n4 = (int)((size_t)EE * CC * HH / 4);
        cvt_k<<<(n4 + 255) / 256, 256>>>((const float4*)w1, (float4*)w1c, n4);
        cvt_k<<<(n4 + 255) / 256, 256>>>((const float4*)w2, (float4*)w2c, n4);
    }

    gemm_k<1><<<dim3(HH / BN, CAP / BM, EE), 256, SMEM_BYTES>>>(b1);
    gemm_k<2><<<dim3(CC / BN, CAP / BM, EE), 256, SMEM_BYTES>>>(b2);
    combine_k<<<(int)(((size_t)NN * CC / 4 + 255) / 256), 256>>>(out);
    aux_k<<<1, 32>>>(out, out_size);
}

// round 5
// speedup vs baseline: 2.0261x; 1.0901x over previous
#include <cuda_runtime.h>
#include <cstdint>
#include <math.h>

#define BB 4
#define TT 4096
#define CC 1024
#define EE 8
#define KKK 2
#define HH 4096
#define NN (BB*TT)
#define CAP 8192

#define BM 128
#define BN 128
#define BK 32
#define STAGES 3
#define A_BYTES (BM*128)                    // 128 rows x 32 tf32 (128B)
#define B_BYTES (BN*128)
#define STAGE_BYTES (A_BYTES + B_BYTES)     // 32768
#define SMEM_BYTES (STAGES*STAGE_BYTES)     // 98304

// ---------------- device scratch ----------------
__device__ int   g_cnt[EE];
__device__ float g_imp[EE];
__device__ int   g_rows[EE*CAP];
__device__ int   g_tokrow[NN*KKK];
__device__ float g_tv[NN*KKK];
__device__ float g_h[(size_t)EE*CAP*HH];      // intermediate (tf32-rounded)
__device__ float g_o[(size_t)EE*CAP*CC];
__device__ float g_xc[(size_t)NN*CC];         // tf32-rounded x
__device__ float g_w1t[(size_t)EE*CC*HH];     // w1^T: [e][n][k], tf32
__device__ float g_w2t[(size_t)EE*HH*CC];     // w2^T: [e][n][k], tf32

__device__ __forceinline__ float tf32r(float v) {
    uint32_t t; asm("cvt.rna.tf32.f32 %0, %1;" : "=r"(t) : "f"(v));
    return __uint_as_float(t);
}
__device__ __forceinline__ void cp16(uint32_t dst, const void* src) {
    asm volatile("cp.async.cg.shared.global [%0], [%1], 16;\n" :: "r"(dst), "l"(src));
}
__device__ __forceinline__ void cp_commit() {
    asm volatile("cp.async.commit_group;\n" ::: "memory");
}
template<int N> __device__ __forceinline__ void cp_wait() {
    asm volatile("cp.async.wait_group %0;\n" :: "n"(N) : "memory");
}
__device__ __forceinline__ void ldsm4(uint32_t& r0, uint32_t& r1, uint32_t& r2, uint32_t& r3,
                                      uint32_t addr) {
    asm volatile("ldmatrix.sync.aligned.m8n8.x4.shared.b16 {%0,%1,%2,%3}, [%4];"
        : "=r"(r0), "=r"(r1), "=r"(r2), "=r"(r3) : "r"(addr));
}

// ---------------- init ----------------
__global__ void init_k() {
    int i = threadIdx.x;
    if (i < EE) { g_cnt[i] = 0; g_imp[i] = 0.f; }
}

// ---------------- x tf32 convert ----------------
__global__ void cvt_k(const float4* __restrict__ src, float4* __restrict__ dst, int n4) {
    int i = blockIdx.x * blockDim.x + threadIdx.x;
    if (i >= n4) return;
    float4 v = src[i];
    float4 o;
    o.x = tf32r(v.x); o.y = tf32r(v.y); o.z = tf32r(v.z); o.w = tf32r(v.w);
    dst[i] = o;
}

// ---------------- weight transpose + tf32: [e][k][n] -> [e][n][k] ----------------
__global__ void tcvt_k(const float* __restrict__ src, float* __restrict__ dst,
                       int Kd, int Nd) {
    __shared__ float t[32][33];
    int e = blockIdx.z;
    src += (size_t)e * Kd * Nd;
    dst += (size_t)e * Kd * Nd;
    int k0 = blockIdx.x * 32, n0 = blockIdx.y * 32;
    int tx = threadIdx.x & 31, ty = threadIdx.x >> 5;
#pragma unroll
    for (int i = 0; i < 32; i += 8)
        t[ty + i][tx] = tf32r(src[(size_t)(k0 + ty + i) * Nd + n0 + tx]);
    __syncthreads();
#pragma unroll
    for (int i = 0; i < 32; i += 8)
        dst[(size_t)(n0 + ty + i) * Kd + k0 + tx] = t[tx][ty + i];
}

// ---------------- router ----------------
__global__ void router_k(const float* __restrict__ x,
                         const float* __restrict__ rw,
                         const float* __restrict__ rb) {
    int gw   = (int)((blockIdx.x * blockDim.x + threadIdx.x) >> 5);
    int lane = threadIdx.x & 31;
    if (gw >= NN) return;
    const float* xr = x + (size_t)gw * CC;

    float acc[EE];
#pragma unroll
    for (int e = 0; e < EE; e++) acc[e] = 0.f;
    for (int c = lane; c < CC; c += 32) {
        float xv = xr[c];
        const float* w = rw + c * EE;
#pragma unroll
        for (int e = 0; e < EE; e++) acc[e] = fmaf(xv, w[e], acc[e]);
    }
#pragma unroll
    for (int e = 0; e < EE; e++) {
#pragma unroll
        for (int off = 16; off; off >>= 1)
            acc[e] += __shfl_xor_sync(0xffffffffu, acc[e], off);
    }
    if (lane == 0) {
        float p[EE];
        float mx = -1e30f;
#pragma unroll
        for (int e = 0; e < EE; e++) { p[e] = acc[e] + rb[e]; mx = fmaxf(mx, p[e]); }
        float s = 0.f;
#pragma unroll
        for (int e = 0; e < EE; e++) { p[e] = expf(p[e] - mx); s += p[e]; }
        float inv = 1.f / s;
#pragma unroll
        for (int e = 0; e < EE; e++) p[e] *= inv;

        int i0 = 0;
#pragma unroll
        for (int e = 1; e < EE; e++) if (p[e] > p[i0]) i0 = e;
        int i1 = (i0 == 0) ? 1 : 0;
#pragma unroll
        for (int e = 0; e < EE; e++) if (e != i0 && p[e] > p[i1]) i1 = e;

        g_tv[gw*2]   = p[i0];
        g_tv[gw*2+1] = p[i1];
        int es[2] = { i0, i1 };
#pragma unroll
        for (int s2 = 0; s2 < 2; s2++) {
            int e = es[s2];
            int pos = atomicAdd(&g_cnt[e], 1);
            if (pos < CAP) {
                g_rows[e*CAP + pos]  = gw;
                g_tokrow[gw*2 + s2]  = e*CAP + pos;
            } else {
                g_tokrow[gw*2 + s2]  = -1;
            }
        }
#pragma unroll
        for (int e = 0; e < EE; e++) atomicAdd(&g_imp[e], p[e]);
    }
}

// ---------------- grouped GEMM, tf32 mma.sync + ldmatrix, 3-stage cp.async ----
// MODE 1: h = relu(gather(xc) @ w1t[e]^T + b1[e])
// MODE 2: o = h @ w2t[e]^T + b2[e]
template<int MODE>
__global__ __launch_bounds__(256, 2)
void gemm_k(const float* __restrict__ bias) {
    constexpr int  Kdim  = (MODE == 1) ? CC : HH;
    constexpr int  outN  = (MODE == 1) ? HH : CC;
    constexpr bool RELU  = (MODE == 1);
    constexpr int  ITERS = Kdim / BK;

    const float* A  = (MODE == 1) ? g_xc : g_h;
    const float* Wt = (MODE == 1) ? g_w1t : g_w2t;
    float*       Out = (MODE == 1) ? g_h : g_o;

    int e   = blockIdx.z;
    int cnt = min(g_cnt[e], CAP);
    int m0  = blockIdx.y * BM;
    if (m0 >= cnt) return;
    int n0  = blockIdx.x * BN;

    extern __shared__ char smem[];
    __shared__ int arow[BM];

    int tid  = threadIdx.x;
    int lane = tid & 31, warp = tid >> 5;

    if (tid < BM) {
        int idx = m0 + tid;
        int g;
        if (MODE == 1) g = (idx < cnt) ? g_rows[e*CAP + idx] : 0;
        else           g = e*CAP + idx;
        arow[tid] = g;
    }
    __syncthreads();

    // ---- cp.async descriptors: 4 A rows + 4 B rows per thread (16B each) ----
    int j  = tid & 7;                 // chunk within 128B row
    int rT = tid >> 3;                // 0..31
    const float* aptr[4]; uint32_t adst[4];
    const float* bptr[4]; uint32_t bdst[4];
#pragma unroll
    for (int i = 0; i < 4; i++) {
        int r = rT + 32*i;
        aptr[i] = A + (size_t)arow[r] * Kdim + j*4;
        adst[i] = (uint32_t)(r*128 + ((j ^ (r & 7)) << 4));
        bptr[i] = Wt + ((size_t)e * outN + n0 + r) * Kdim + j*4;
        bdst[i] = (uint32_t)(A_BYTES + r*128 + ((j ^ (r & 7)) << 4));
    }

    uint32_t smbase = (uint32_t)__cvta_generic_to_shared(smem);

    auto issue = [&](int stage) {
        uint32_t s = smbase + (uint32_t)stage * STAGE_BYTES;
#pragma unroll
        for (int i = 0; i < 4; i++) { cp16(s + adst[i], aptr[i]); aptr[i] += BK; }
#pragma unroll
        for (int i = 0; i < 4; i++) { cp16(s + bdst[i], bptr[i]); bptr[i] += BK; }
    };

    issue(0); cp_commit();
    issue(1); cp_commit();

    // ---- ldmatrix per-lane address components ----
    int wm = (warp & 3) * 32;
    int wn = (warp >> 2) * 64;
    int sl   = lane & 7;              // row-within-8 AND swizzle key
    int mi   = lane >> 3;             // matrix index 0..3
    int chiA = mi >> 1;               // chunk add for A matrices
    int chiB = mi & 1;                // chunk add for B matrices
    // A row offsets for mt=0,1 : rm = wm + mt*16 + ((mi&1)<<3) + sl
    uint32_t aoff[2];
#pragma unroll
    for (int mt = 0; mt < 2; mt++)
        aoff[mt] = (uint32_t)((wm + mt*16 + ((mi & 1) << 3) + sl) * 128);
    // B row offsets for pair p=0..3 : rn = wn + p*16 + ((mi>>1)<<3) + sl
    uint32_t boff[4];
#pragma unroll
    for (int p = 0; p < 4; p++)
        boff[p] = (uint32_t)(A_BYTES + (wn + p*16 + ((mi >> 1) << 3) + sl) * 128);

    float acc[2][8][4];
#pragma unroll
    for (int mt = 0; mt < 2; mt++)
#pragma unroll
        for (int nt = 0; nt < 8; nt++)
#pragma unroll
            for (int q = 0; q < 4; q++) acc[mt][nt][q] = 0.f;

    for (int it = 0; it < ITERS; ++it) {
        cp_wait<1>();
        __syncthreads();
        if (it + 2 < ITERS) issue((it + 2) % STAGES);
        cp_commit();

        uint32_t stg = smbase + (uint32_t)(it % STAGES) * STAGE_BYTES;

#pragma unroll
        for (int ks = 0; ks < BK; ks += 8) {
            const int c0 = ks >> 2;
            uint32_t af[2][4], bf[8][2];
#pragma unroll
            for (int mt = 0; mt < 2; mt++)
                ldsm4(af[mt][0], af[mt][1], af[mt][2], af[mt][3],
                      stg + aoff[mt] + (uint32_t)(((c0 + chiA) ^ sl) << 4));
#pragma unroll
            for (int p = 0; p < 4; p++)
                ldsm4(bf[2*p][0], bf[2*p][1], bf[2*p+1][0], bf[2*p+1][1],
                      stg + boff[p] + (uint32_t)(((c0 + chiB) ^ sl) << 4));
#pragma unroll
            for (int mt = 0; mt < 2; mt++)
#pragma unroll
                for (int nt = 0; nt < 8; nt++) {
                    asm volatile(
                        "mma.sync.aligned.m16n8k8.row.col.f32.tf32.tf32.f32 "
                        "{%0,%1,%2,%3}, {%4,%5,%6,%7}, {%8,%9}, {%0,%1,%2,%3};"
                        : "+f"(acc[mt][nt][0]), "+f"(acc[mt][nt][1]),
                          "+f"(acc[mt][nt][2]), "+f"(acc[mt][nt][3])
                        : "r"(af[mt][0]), "r"(af[mt][1]), "r"(af[mt][2]), "r"(af[mt][3]),
                          "r"(bf[nt][0]), "r"(bf[nt][1]));
                }
        }
    }

    // ---- epilogue ----
    int q  = lane & 3;
    int gg = lane >> 2;
#pragma unroll
    for (int mt = 0; mt < 2; mt++)
#pragma unroll
        for (int nt = 0; nt < 8; nt++) {
            int mrow = wm + mt*16 + gg;
            int col  = n0 + wn + nt*8 + 2*q;
            float bc0 = bias[e * outN + col];
            float bc1 = bias[e * outN + col + 1];
            float v00 = acc[mt][nt][0] + bc0;
            float v01 = acc[mt][nt][1] + bc1;
            float v10 = acc[mt][nt][2] + bc0;
            float v11 = acc[mt][nt][3] + bc1;
            if (RELU) {
                v00 = tf32r(fmaxf(v00, 0.f)); v01 = tf32r(fmaxf(v01, 0.f));
                v10 = tf32r(fmaxf(v10, 0.f)); v11 = tf32r(fmaxf(v11, 0.f));
            }
            size_t o0 = ((size_t)(e * CAP + m0 + mrow)) * outN + col;
            Out[o0]     = v00; Out[o0 + 1] = v01;
            size_t o1 = o0 + (size_t)8 * outN;
            Out[o1]     = v10; Out[o1 + 1] = v11;
        }
}

// ---------------- combine ----------------
__global__ void combine_k(float* __restrict__ out) {
    size_t i = (size_t)blockIdx.x * blockDim.x + threadIdx.x;
    if (i >= (size_t)NN * CC / 4) return;
    int t  = (int)(i / (CC / 4));
    int c  = (int)(i % (CC / 4)) * 4;
    float w = g_tv[t];
    int r0 = g_tokrow[t * 2];
    int r1 = g_tokrow[t * 2 + 1];
    float4 a = make_float4(0.f, 0.f, 0.f, 0.f);
    float4 b = make_float4(0.f, 0.f, 0.f, 0.f);
    if (r0 >= 0) a = *(const float4*)(g_o + (size_t)r0 * CC + c);
    if (r1 >= 0) b = *(const float4*)(g_o + (size_t)r1 * CC + c);
    float4 o;
    o.x = w * (a.x + b.x); o.y = w * (a.y + b.y);
    o.z = w * (a.z + b.z); o.w = w * (a.w + b.w);
    *(float4*)(out + (size_t)t * CC + c) = o;
}

// ---------------- aux loss ----------------
__global__ void aux_k(float* __restrict__ out, int out_size) {
    int lane = threadIdx.x;
    float v = 0.f;
    if (lane < EE)
        v = (g_imp[lane] / (float)NN) * ((float)g_cnt[lane] / (float)(NN * KKK));
#pragma unroll
    for (int off = 16; off; off >>= 1) v += __shfl_xor_sync(0xffffffffu, v, off);
    if (lane == 0) {
        if (out_size > NN * CC)     out[(size_t)NN * CC] = v;
        if (out_size - 1 > NN * CC) out[(size_t)out_size - 1] = v;
    }
}

// ---------------- launch ----------------
extern "C" void kernel_launch(void* const* d_in, const int* in_sizes, int n_in,
                              void* d_out, int out_size) {
    const float* x  = (const float*)d_in[0];
    const float* rw = (const float*)d_in[1];
    const float* rb = (const float*)d_in[2];
    const float* w1 = (const float*)d_in[3];
    const float* b1 = (const float*)d_in[4];
    const float* w2 = (const float*)d_in[5];
    const float* b2 = (const float*)d_in[6];
    float* out = (float*)d_out;

    cudaFuncSetAttribute(gemm_k<1>, cudaFuncAttributeMaxDynamicSharedMemorySize, SMEM_BYTES);
    cudaFuncSetAttribute(gemm_k<2>, cudaFuncAttributeMaxDynamicSharedMemorySize, SMEM_BYTES);

    float* xc;  cudaGetSymbolAddress((void**)&xc,  g_xc);
    float* w1t; cudaGetSymbolAddress((void**)&w1t, g_w1t);
    float* w2t; cudaGetSymbolAddress((void**)&w2t, g_w2t);

    init_k<<<1, 32>>>();
    router_k<<<NN / 8, 256>>>(x, rw, rb);

    {
        int n4 = (int)((size_t)NN * CC / 4);
        cvt_k<<<(n4 + 255) / 256, 256>>>((const float4*)x, (float4*)xc, n4);
    }
    tcvt_k<<<dim3(CC/32, HH/32, EE), 256>>>(w1, w1t, CC, HH);
    tcvt_k<<<dim3(HH/32, CC/32, EE), 256>>>(w2, w2t, HH, CC);

    gemm_k<1><<<dim3(HH / BN, CAP / BM, EE), 256, SMEM_BYTES>>>(b1);
    gemm_k<2><<<dim3(CC / BN, CAP / BM, EE), 256, SMEM_BYTES>>>(b2);
    combine_k<<<(int)(((size_t)NN * CC / 4 + 255) / 256), 256>>>(out);
    aux_k<<<1, 32>>>(out, out_size);
}

// round 7
// speedup vs baseline: 3.3098x; 1.6336x over previous
#include <cuda_runtime.h>
#include <cuda_fp16.h>
#include <cstdint>
#include <math.h>

#define BB 4
#define TT 4096
#define CC 1024
#define EE 8
#define KKK 2
#define HH 4096
#define NN (BB*TT)
#define CAP 8192

#define BM 128
#define BN 128
#define BK 64                               // halves per stage (128B rows)
#define STAGES 3
#define A_BYTES (BM*128)
#define B_BYTES (BN*128)
#define STAGE_BYTES (A_BYTES + B_BYTES)     // 32768
#define SMEM_BYTES (STAGES*STAGE_BYTES)     // 98304

// ---------------- device scratch ----------------
__device__ int    g_cnt[EE];
__device__ float  g_imp[EE];
__device__ int    g_rows[EE*CAP];
__device__ int    g_tokrow[NN*KKK];
__device__ float  g_tv[NN*KKK];
__device__ __half g_hh[(size_t)EE*CAP*HH];     // intermediate (fp16)
__device__ float  g_o[(size_t)EE*CAP*CC];
__device__ __half g_xh[(size_t)NN*CC];         // fp16 x
__device__ __half g_w1h[(size_t)EE*CC*HH];     // w1^T: [e][n][k], fp16
__device__ __half g_w2h[(size_t)EE*HH*CC];     // w2^T: [e][n][k], fp16

__device__ __forceinline__ uint32_t pack_h2(float lo, float hi) {
    union { __half2 h; uint32_t u; } cv;
    cv.h = __floats2half2_rn(lo, hi);
    return cv.u;
}
__device__ __forceinline__ void cp16(uint32_t dst, const void* src) {
    asm volatile("cp.async.cg.shared.global [%0], [%1], 16;\n" :: "r"(dst), "l"(src));
}
__device__ __forceinline__ void cp_commit() {
    asm volatile("cp.async.commit_group;\n" ::: "memory");
}
template<int N> __device__ __forceinline__ void cp_wait() {
    asm volatile("cp.async.wait_group %0;\n" :: "n"(N) : "memory");
}
__device__ __forceinline__ void ldsm4(uint32_t& r0, uint32_t& r1, uint32_t& r2, uint32_t& r3,
                                      uint32_t addr) {
    asm volatile("ldmatrix.sync.aligned.m8n8.x4.shared.b16 {%0,%1,%2,%3}, [%4];"
        : "=r"(r0), "=r"(r1), "=r"(r2), "=r"(r3) : "r"(addr));
}

// ---------------- init ----------------
__global__ void init_k() {
    int i = threadIdx.x;
    if (i < EE) { g_cnt[i] = 0; g_imp[i] = 0.f; }
}

// ---------------- x -> fp16 ----------------
__global__ void cvt_h(const float4* __restrict__ src, uint4* __restrict__ dst, int n8) {
    int i = blockIdx.x * blockDim.x + threadIdx.x;
    if (i >= n8) return;
    float4 a = src[2*i], b = src[2*i+1];
    uint4 o;
    o.x = pack_h2(a.x, a.y);
    o.y = pack_h2(a.z, a.w);
    o.z = pack_h2(b.x, b.y);
    o.w = pack_h2(b.z, b.w);
    dst[i] = o;
}

// ---------------- weight transpose + fp16: [e][k][n] -> [e][n][k] ----------------
__global__ void tcvt_h(const float* __restrict__ src, __half* __restrict__ dst,
                       int Kd, int Nd) {
    __shared__ float t[32][33];
    int e = blockIdx.z;
    src += (size_t)e * Kd * Nd;
    dst += (size_t)e * Kd * Nd;
    int k0 = blockIdx.x * 32, n0 = blockIdx.y * 32;
    int tx = threadIdx.x & 31, ty = threadIdx.x >> 5;
#pragma unroll
    for (int i = 0; i < 32; i += 8)
        t[ty + i][tx] = src[(size_t)(k0 + ty + i) * Nd + n0 + tx];
    __syncthreads();
#pragma unroll
    for (int i = 0; i < 32; i += 8)
        dst[(size_t)(n0 + ty + i) * Kd + k0 + tx] = __float2half_rn(t[tx][ty + i]);
}

// ---------------- router ----------------
__global__ void router_k(const float* __restrict__ x,
                         const float* __restrict__ rw,
                         const float* __restrict__ rb) {
    int gw   = (int)((blockIdx.x * blockDim.x + threadIdx.x) >> 5);
    int lane = threadIdx.x & 31;
    if (gw >= NN) return;
    const float* xr = x + (size_t)gw * CC;

    float acc[EE];
#pragma unroll
    for (int e = 0; e < EE; e++) acc[e] = 0.f;
    for (int c = lane; c < CC; c += 32) {
        float xv = xr[c];
        const float* w = rw + c * EE;
#pragma unroll
        for (int e = 0; e < EE; e++) acc[e] = fmaf(xv, w[e], acc[e]);
    }
#pragma unroll
    for (int e = 0; e < EE; e++) {
#pragma unroll
        for (int off = 16; off; off >>= 1)
            acc[e] += __shfl_xor_sync(0xffffffffu, acc[e], off);
    }
    if (lane == 0) {
        float p[EE];
        float mx = -1e30f;
#pragma unroll
        for (int e = 0; e < EE; e++) { p[e] = acc[e] + rb[e]; mx = fmaxf(mx, p[e]); }
        float s = 0.f;
#pragma unroll
        for (int e = 0; e < EE; e++) { p[e] = expf(p[e] - mx); s += p[e]; }
        float inv = 1.f / s;
#pragma unroll
        for (int e = 0; e < EE; e++) p[e] *= inv;

        int i0 = 0;
#pragma unroll
        for (int e = 1; e < EE; e++) if (p[e] > p[i0]) i0 = e;
        int i1 = (i0 == 0) ? 1 : 0;
#pragma unroll
        for (int e = 0; e < EE; e++) if (e != i0 && p[e] > p[i1]) i1 = e;

        g_tv[gw*2]   = p[i0];
        g_tv[gw*2+1] = p[i1];
        int es[2] = { i0, i1 };
#pragma unroll
        for (int s2 = 0; s2 < 2; s2++) {
            int e = es[s2];
            int pos = atomicAdd(&g_cnt[e], 1);
            if (pos < CAP) {
                g_rows[e*CAP + pos]  = gw;
                g_tokrow[gw*2 + s2]  = e*CAP + pos;
            } else {
                g_tokrow[gw*2 + s2]  = -1;
            }
        }
#pragma unroll
        for (int e = 0; e < EE; e++) atomicAdd(&g_imp[e], p[e]);
    }
}

// ---------------- grouped GEMM, fp16 m16n8k16 + ldmatrix, 3-stage cp.async ----
// MODE 1: h = relu(gather(xh) @ w1h[e]^T + b1[e])  -> fp16
// MODE 2: o = h @ w2h[e]^T + b2[e]                  -> fp32
template<int MODE>
__global__ __launch_bounds__(256, 2)
void gemm_k(const float* __restrict__ bias) {
    constexpr int  Kdim  = (MODE == 1) ? CC : HH;
    constexpr int  outN  = (MODE == 1) ? HH : CC;
    constexpr int  ITERS = Kdim / BK;

    const __half* A  = (MODE == 1) ? g_xh : g_hh;
    const __half* Wt = (MODE == 1) ? g_w1h : g_w2h;

    int e   = blockIdx.z;
    int cnt = min(g_cnt[e], CAP);
    int m0  = blockIdx.y * BM;
    if (m0 >= cnt) return;
    int n0  = blockIdx.x * BN;

    extern __shared__ char smem[];
    __shared__ int arow[BM];

    int tid  = threadIdx.x;
    int lane = tid & 31, warp = tid >> 5;

    if (tid < BM) {
        int idx = m0 + tid;
        int g;
        if (MODE == 1) g = (idx < cnt) ? g_rows[e*CAP + idx] : 0;
        else           g = e*CAP + idx;
        arow[tid] = g;
    }
    __syncthreads();

    // ---- cp.async descriptors: 4 A chunks + 4 B chunks per thread (16B) ----
    int j  = tid & 7;
    int rT = tid >> 3;
    const __half* aptr[4]; uint32_t adst[4];
    const __half* bptr[4]; uint32_t bdst[4];
#pragma unroll
    for (int i = 0; i < 4; i++) {
        int r = rT + 32*i;
        aptr[i] = A + (size_t)arow[r] * Kdim + j*8;
        adst[i] = (uint32_t)(r*128 + ((j ^ (r & 7)) << 4));
        bptr[i] = Wt + ((size_t)e * outN + n0 + r) * Kdim + j*8;
        bdst[i] = (uint32_t)(A_BYTES + r*128 + ((j ^ (r & 7)) << 4));
    }

    uint32_t smbase = (uint32_t)__cvta_generic_to_shared(smem);

    auto issue = [&](int stage) {
        uint32_t s = smbase + (uint32_t)stage * STAGE_BYTES;
#pragma unroll
        for (int i = 0; i < 4; i++) { cp16(s + adst[i], aptr[i]); aptr[i] += BK; }
#pragma unroll
        for (int i = 0; i < 4; i++) { cp16(s + bdst[i], bptr[i]); bptr[i] += BK; }
    };

    issue(0); cp_commit();
    issue(1); cp_commit();

    // ---- ldmatrix per-lane components ----
    int wm  = (warp & 3) * 32;
    int wn  = (warp >> 2) * 64;
    int r16 = lane & 15;
    int coff = lane >> 4;             // 0/1 : k-half select
    int sl7  = lane & 7;              // swizzle key of the addressed row
    uint32_t aoff[2];
#pragma unroll
    for (int mt = 0; mt < 2; mt++)
        aoff[mt] = (uint32_t)((wm + mt*16 + r16) * 128);
    uint32_t boff[4];
#pragma unroll
    for (int p = 0; p < 4; p++)
        boff[p] = (uint32_t)(A_BYTES + (wn + p*16 + r16) * 128);

    float acc[2][8][4];
#pragma unroll
    for (int mt = 0; mt < 2; mt++)
#pragma unroll
        for (int nt = 0; nt < 8; nt++)
#pragma unroll
            for (int q = 0; q < 4; q++) acc[mt][nt][q] = 0.f;

    for (int it = 0; it < ITERS; ++it) {
        cp_wait<1>();
        __syncthreads();
        if (it + 2 < ITERS) issue((it + 2) % STAGES);
        cp_commit();

        uint32_t stg = smbase + (uint32_t)(it % STAGES) * STAGE_BYTES;

#pragma unroll
        for (int ks = 0; ks < BK; ks += 16) {
            const int c0 = (ks >> 3) + coff;
            const uint32_t csw = (uint32_t)((c0 ^ sl7) << 4);
            uint32_t af[2][4], bf[8][2];
#pragma unroll
            for (int mt = 0; mt < 2; mt++)
                ldsm4(af[mt][0], af[mt][1], af[mt][2], af[mt][3],
                      stg + aoff[mt] + csw);
#pragma unroll
            for (int p = 0; p < 4; p++)
                ldsm4(bf[2*p][0], bf[2*p+1][0], bf[2*p][1], bf[2*p+1][1],
                      stg + boff[p] + csw);
#pragma unroll
            for (int mt = 0; mt < 2; mt++)
#pragma unroll
                for (int nt = 0; nt < 8; nt++) {
                    asm volatile(
                        "mma.sync.aligned.m16n8k16.row.col.f32.f16.f16.f32 "
                        "{%0,%1,%2,%3}, {%4,%5,%6,%7}, {%8,%9}, {%0,%1,%2,%3};"
                        : "+f"(acc[mt][nt][0]), "+f"(acc[mt][nt][1]),
                          "+f"(acc[mt][nt][2]), "+f"(acc[mt][nt][3])
                        : "r"(af[mt][0]), "r"(af[mt][1]), "r"(af[mt][2]), "r"(af[mt][3]),
                          "r"(bf[nt][0]), "r"(bf[nt][1]));
                }
        }
    }

    // ---- epilogue ----
    int q  = lane & 3;
    int gg = lane >> 2;
#pragma unroll
    for (int mt = 0; mt < 2; mt++)
#pragma unroll
        for (int nt = 0; nt < 8; nt++) {
            int mrow = wm + mt*16 + gg;
            int col  = n0 + wn + nt*8 + 2*q;
            float bc0 = bias[e * outN + col];
            float bc1 = bias[e * outN + col + 1];
            float v00 = acc[mt][nt][0] + bc0;
            float v01 = acc[mt][nt][1] + bc1;
            float v10 = acc[mt][nt][2] + bc0;
            float v11 = acc[mt][nt][3] + bc1;
            size_t o0 = ((size_t)(e * CAP + m0 + mrow)) * outN + col;
            size_t o1 = o0 + (size_t)8 * outN;
            if (MODE == 1) {
                uint32_t h0 = pack_h2(fmaxf(v00, 0.f), fmaxf(v01, 0.f));
                uint32_t h1 = pack_h2(fmaxf(v10, 0.f), fmaxf(v11, 0.f));
                *(uint32_t*)(g_hh + o0) = h0;
                *(uint32_t*)(g_hh + o1) = h1;
            } else {
                g_o[o0] = v00; g_o[o0 + 1] = v01;
                g_o[o1] = v10; g_o[o1 + 1] = v11;
            }
        }
}

// ---------------- combine ----------------
__global__ void combine_k(float* __restrict__ out) {
    size_t i = (size_t)blockIdx.x * blockDim.x + threadIdx.x;
    if (i >= (size_t)NN * CC / 4) return;
    int t  = (int)(i / (CC / 4));
    int c  = (int)(i % (CC / 4)) * 4;
    float w = g_tv[t];
    int r0 = g_tokrow[t * 2];
    int r1 = g_tokrow[t * 2 + 1];
    float4 a = make_float4(0.f, 0.f, 0.f, 0.f);
    float4 b = make_float4(0.f, 0.f, 0.f, 0.f);
    if (r0 >= 0) a = *(const float4*)(g_o + (size_t)r0 * CC + c);
    if (r1 >= 0) b = *(const float4*)(g_o + (size_t)r1 * CC + c);
    float4 o;
    o.x = w * (a.x + b.x); o.y = w * (a.y + b.y);
    o.z = w * (a.z + b.z); o.w = w * (a.w + b.w);
    *(float4*)(out + (size_t)t * CC + c) = o;
}

// ---------------- aux loss ----------------
__global__ void aux_k(float* __restrict__ out, int out_size) {
    int lane = threadIdx.x;
    float v = 0.f;
    if (lane < EE)
        v = (g_imp[lane] / (float)NN) * ((float)g_cnt[lane] / (float)(NN * KKK));
#pragma unroll
    for (int off = 16; off; off >>= 1) v += __shfl_xor_sync(0xffffffffu, v, off);
    if (lane == 0) {
        if (out_size > NN * CC)     out[(size_t)NN * CC] = v;
        if (out_size - 1 > NN * CC) out[(size_t)out_size - 1] = v;
    }
}

// ---------------- launch ----------------
extern "C" void kernel_launch(void* const* d_in, const int* in_sizes, int n_in,
                              void* d_out, int out_size) {
    const float* x  = (const float*)d_in[0];
    const float* rw = (const float*)d_in[1];
    const float* rb = (const float*)d_in[2];
    const float* w1 = (const float*)d_in[3];
    const float* b1 = (const float*)d_in[4];
    const float* w2 = (const float*)d_in[5];
    const float* b2 = (const float*)d_in[6];
    float* out = (float*)d_out;

    cudaFuncSetAttribute(gemm_k<1>, cudaFuncAttributeMaxDynamicSharedMemorySize, SMEM_BYTES);
    cudaFuncSetAttribute(gemm_k<2>, cudaFuncAttributeMaxDynamicSharedMemorySize, SMEM_BYTES);

    __half* xh;  cudaGetSymbolAddress((void**)&xh,  g_xh);
    __half* w1h; cudaGetSymbolAddress((void**)&w1h, g_w1h);
    __half* w2h; cudaGetSymbolAddress((void**)&w2h, g_w2h);

    init_k<<<1, 32>>>();
    router_k<<<NN / 8, 256>>>(x, rw, rb);

    {
        int n8 = (int)((size_t)NN * CC / 8);
        cvt_h<<<(n8 + 255) / 256, 256>>>((const float4*)x, (uint4*)xh, n8);
    }
    tcvt_h<<<dim3(CC/32, HH/32, EE), 256>>>(w1, w1h, CC, HH);
    tcvt_h<<<dim3(HH/32, CC/32, EE), 256>>>(w2, w2h, HH, CC);

    gemm_k<1><<<dim3(HH / BN, CAP / BM, EE), 256, SMEM_BYTES>>>(b1);
    gemm_k<2><<<dim3(CC / BN, CAP / BM, EE), 256, SMEM_BYTES>>>(b2);
    combine_k<<<(int)(((size_t)NN * CC / 4 + 255) / 256), 256>>>(out);
    aux_k<<<1, 32>>>(out, out_size);
}